// round 9
// baseline (speedup 1.0000x reference)
#include <cuda_runtime.h>
#include <cuda_bf16.h>
#include <cstdint>

#define N_TOT  32768
#define DIM    64
#define KCODES 1024
#define BM     128
#define NTHR   256
#define NCHUNK 8      // HMMA: 1024 codes / 128
#define NCK    128
#define HB     152    // blocks 0..HB-1 -> HMMA path; rest -> FFMA path

// output offsets (float32 elements), concatenated in reference return order
#define O_QV   0
#define O_IDX  2097152
#define O_LOSS 2129920
#define O_EMB  2129921     // ODD offset -> scalar stores only
#define O_CL   2195457
#define O_EMA  2196481     // ODD offset -> scalar stores only

typedef unsigned long long u64;
typedef unsigned int u32;

// ---- scratch (__device__ globals; no allocations allowed) ----
__device__ float g_dw[KCODES * DIM];
__device__ float g_ni[KCODES];
__device__ float g_ee[KCODES];
__device__ float g_loss;
__device__ uint4 g_esplit[3][KCODES * 8];   // 3 bf16 split terms

// ---- smem (dynamic, 102400 B -> 2 blocks/SM) ----
#define A_OFF    0          // HMMA: 3 x 16KB bf16 A tiles | FFMA: zs fp32 32KB
#define B_OFF    49152      // HMMA: 3 x 16KB bf16 B tiles | FFMA: es 16KB
#define EE_OFF   98304      // 1024 floats ||e||^2
#define SMEM_SZ  102400

#define SW128(b) ((b) ^ (((b) >> 3) & 0x70))

__device__ __forceinline__ u32 smem_u32(const void* p) {
    u32 a;
    asm("{ .reg .u64 t; cvta.to.shared.u64 t, %1; cvt.u32.u64 %0, t; }" : "=r"(a) : "l"(p));
    return a;
}
#define LDSM_X4(r, addr) \
    asm volatile("ldmatrix.sync.aligned.m8n8.x4.shared.b16 {%0,%1,%2,%3}, [%4];" \
        : "=r"((r)[0]), "=r"((r)[1]), "=r"((r)[2]), "=r"((r)[3]) : "r"(addr))
#define MMA_BF16(c, a, b0, b1) \
    asm volatile("mma.sync.aligned.m16n8k16.row.col.f32.bf16.bf16.f32 " \
        "{%0,%1,%2,%3}, {%4,%5,%6,%7}, {%8,%9}, {%0,%1,%2,%3};" \
        : "+f"((c)[0]), "+f"((c)[1]), "+f"((c)[2]), "+f"((c)[3]) \
        : "r"((a)[0]), "r"((a)[1]), "r"((a)[2]), "r"((a)[3]), \
          "r"(b0), "r"(b1))

__device__ __forceinline__ void split3(float x, u32& h0, u32& h1, u32& h2) {
    __nv_bfloat16 b0 = __float2bfloat16(x);
    float f0 = __bfloat162float(b0);
    float r = x - f0;
    __nv_bfloat16 b1 = __float2bfloat16(r);
    float f1 = __bfloat162float(b1);
    __nv_bfloat16 b2 = __float2bfloat16(r - f1);
    h0 = (u32)__bfloat16_as_ushort(b0);
    h1 = (u32)__bfloat16_as_ushort(b1);
    h2 = (u32)__bfloat16_as_ushort(b2);
}
__device__ __forceinline__ float bf_lo(u32 w) {
    return __bfloat162float(__ushort_as_bfloat16((unsigned short)(w & 0xffffu)));
}
__device__ __forceinline__ float bf_hi(u32 w) {
    return __bfloat162float(__ushort_as_bfloat16((unsigned short)(w >> 16)));
}
__device__ __forceinline__ u64 pack_key(float v, u32 k) {
    u32 u = __float_as_uint(v);
    u = (u & 0x80000000u) ? ~u : (u | 0x80000000u);
    return ((u64)u << 32) | (u64)k;
}
__device__ __forceinline__ u64 dup_f(float a) {
    u64 r; asm("mov.b64 %0, {%1,%1};" : "=l"(r) : "f"(a)); return r;
}
__device__ __forceinline__ u64 pk2(float a, float b) {
    u64 r; asm("mov.b64 %0, {%1,%2};" : "=l"(r) : "f"(a), "f"(b)); return r;
}
__device__ __forceinline__ void fma2(u64& acc, u64 a, u64 b) {
    asm("fma.rn.f32x2 %0, %1, %2, %0;" : "+l"(acc) : "l"(a), "l"(b));
}
__device__ __forceinline__ void unpk(u64 v, float& lo, float& hi) {
    asm("mov.b64 {%0,%1}, %2;" : "=f"(lo), "=f"(hi) : "l"(v));
}

// ---------------------------------------------------------------------------
// Kernel 0: zero scratch, ||e||^2, split embeddings into 3 bf16 arrays
// ---------------------------------------------------------------------------
__global__ void k_prep(const float* __restrict__ emb) {
    int t = blockIdx.x * blockDim.x + threadIdx.x;   // 16384 threads
    reinterpret_cast<float4*>(g_dw)[t] = make_float4(0.f, 0.f, 0.f, 0.f);
    {
        int code = t >> 4, dq = t & 15;
        float4 v = __ldg(reinterpret_cast<const float4*>(emb) + t);
        u32 h0[4], h1[4], h2[4];
        split3(v.x, h0[0], h1[0], h2[0]);
        split3(v.y, h0[1], h1[1], h2[1]);
        split3(v.z, h0[2], h1[2], h2[2]);
        split3(v.w, h0[3], h1[3], h2[3]);
        u32 base = code * 32 + dq * 2;
        u32* p0 = reinterpret_cast<u32*>(g_esplit[0]);
        u32* p1 = reinterpret_cast<u32*>(g_esplit[1]);
        u32* p2 = reinterpret_cast<u32*>(g_esplit[2]);
        p0[base] = h0[0] | (h0[1] << 16);  p0[base + 1] = h0[2] | (h0[3] << 16);
        p1[base] = h1[0] | (h1[1] << 16);  p1[base + 1] = h1[2] | (h1[3] << 16);
        p2[base] = h2[0] | (h2[1] << 16);  p2[base + 1] = h2[2] | (h2[3] << 16);
    }
    if (t < KCODES) {
        g_ni[t] = 0.0f;
        const float4* e4 = reinterpret_cast<const float4*>(emb + (size_t)t * DIM);
        float s = 0.0f;
#pragma unroll
        for (int i = 0; i < 16; i++) {
            float4 v = e4[i];
            s += v.x * v.x + v.y * v.y + v.z * v.z + v.w * v.w;
        }
        g_ee[t] = s;
    }
    if (t == 0) g_loss = 0.0f;
}

// ---------------------------------------------------------------------------
// Kernel 1: hybrid — blocks < HB run tensor-pipe HMMA path, rest run fma-pipe
// FFMA2 path. Disjoint rows, different execution pipes -> co-resident overlap.
// ---------------------------------------------------------------------------
__global__ __launch_bounds__(NTHR, 2)
void k_main(const float* __restrict__ z, const float* __restrict__ emb,
            float* __restrict__ out) {
    extern __shared__ __align__(16) unsigned char sm[];
    const u32 smb = smem_u32(sm);
    const int tid  = threadIdx.x;
    const int lane = tid & 31;
    const int wid  = tid >> 5;
    const int row0 = blockIdx.x * BM;

    if (blockIdx.x < HB) {
        // =================== HMMA path (tensor pipe) =====================
        int*   sidx = reinterpret_cast<int*>(sm + B_OFF);
        float* lred = reinterpret_cast<float*>(sm + B_OFF + 2048);
        float* ees  = reinterpret_cast<float*>(sm + EE_OFF);
        const int wrow = wid * 16;

        for (int i = tid; i < KCODES; i += NTHR) ees[i] = __ldg(&g_ee[i]);

        for (int i = tid; i < BM * 16; i += NTHR) {
            int m = i >> 4, dq = i & 15;
            float4 v = *reinterpret_cast<const float4*>(z + (size_t)(row0 + m) * DIM + dq * 4);
            u32 h0[4], h1[4], h2[4];
            split3(v.x, h0[0], h1[0], h2[0]);
            split3(v.y, h0[1], h1[1], h2[1]);
            split3(v.z, h0[2], h1[2], h2[2]);
            split3(v.w, h0[3], h1[3], h2[3]);
            u32 sw = SW128((u32)(m * 128 + dq * 8));
#pragma unroll
            for (int t = 0; t < 3; t++) {
                u32* hh = (t == 0) ? h0 : (t == 1) ? h1 : h2;
                u32* dst = reinterpret_cast<u32*>(sm + A_OFF + t * 16384 + sw);
                dst[0] = hh[0] | (hh[1] << 16);
                dst[1] = hh[2] | (hh[3] << 16);
            }
        }
        __syncthreads();

        u32 afr[3][4][4];
        {
            int g = lane >> 3;
            int arow = wrow + (g & 1) * 8 + (lane & 7);
            int acol = (g >> 1) * 16;
#pragma unroll
            for (int t = 0; t < 3; t++)
#pragma unroll
                for (int kt = 0; kt < 4; kt++) {
                    u32 addr = smb + A_OFF + t * 16384 +
                               SW128((u32)(arow * 128 + kt * 32 + acol));
                    LDSM_X4(afr[t][kt], addr);
                }
        }

        float best0 = 3.4e38f, best1 = 3.4e38f;
        u32   idx0 = 0, idx1 = 0;
        const int brow    = lane & 7;
        const int bcolsel = ((lane >> 3) & 1) * 16;
        const int btile   = (lane >> 4) * 8;
        const int term_order[6] = {0, 3, 1, 4, 2, 5};
        const int TA[6] = {2, 0, 1, 1, 0, 0};
        const int TB[6] = {0, 2, 1, 0, 1, 0};

        for (int c = 0; c < NCHUNK; c++) {
            __syncthreads();
            for (int u = tid; u < 3072; u += NTHR) {
                int term = u >> 10;
                int rem  = u & 1023;
                int krow = rem >> 3;
                int seg  = rem & 7;
                uint4 v = __ldg(&g_esplit[term][(c * NCK + krow) * 8 + seg]);
                u32 sw = SW128((u32)(krow * 128 + seg * 16));
                *reinterpret_cast<uint4*>(sm + B_OFF + term * 16384 + sw) = v;
            }
            __syncthreads();

            for (int p = 0; p < 8; p++) {
                float ccA0[4] = {0, 0, 0, 0}, ccA1[4] = {0, 0, 0, 0};
                float ccB0[4] = {0, 0, 0, 0}, ccB1[4] = {0, 0, 0, 0};
                int rbase = (p * 16 + btile + brow) * 128 + bcolsel;
#pragma unroll
                for (int h = 0; h < 2; h++) {
                    u32 bb[3][2][4];
#pragma unroll
                    for (int t = 0; t < 3; t++)
#pragma unroll
                        for (int q = 0; q < 2; q++) {
                            int kt = h * 2 + q;
                            u32 addr = smb + B_OFF + t * 16384 +
                                       SW128((u32)(rbase + kt * 32));
                            LDSM_X4(bb[t][q], addr);
                        }
#pragma unroll
                    for (int q = 0; q < 2; q++) {
                        int kt = h * 2 + q;
#pragma unroll
                        for (int o = 0; o < 6; o++) {
                            int t = term_order[o];
                            const u32* a = afr[TA[t]][kt];
                            const u32* b = bb[TB[t]][q];
                            if (t < 3) {
                                MMA_BF16(ccA0, a, b[0], b[1]);
                                MMA_BF16(ccB0, a, b[2], b[3]);
                            } else {
                                MMA_BF16(ccA1, a, b[0], b[1]);
                                MMA_BF16(ccB1, a, b[2], b[3]);
                            }
                        }
                    }
                }

                u32 kcA = (u32)(c * NCK + p * 16 + 2 * (lane & 3));
                u32 kcB = kcA + 8;
                float eA0 = ees[kcA], eA1 = ees[kcA + 1];
                float eB0 = ees[kcB], eB1 = ees[kcB + 1];
#pragma unroll
                for (int half = 0; half < 2; half++) {
                    float c0 = (half ? ccA0[2] + ccA1[2] : ccA0[0] + ccA1[0]);
                    float c1 = (half ? ccA0[3] + ccA1[3] : ccA0[1] + ccA1[1]);
                    float d0 = fmaf(-2.0f, c0, eA0);
                    float d1 = fmaf(-2.0f, c1, eA1);
                    float cv = (d1 < d0) ? d1 : d0;
                    u32   ck = (d1 < d0) ? kcA + 1 : kcA;
                    if (half == 0) { if (cv < best0) { best0 = cv; idx0 = ck; } }
                    else           { if (cv < best1) { best1 = cv; idx1 = ck; } }
                }
#pragma unroll
                for (int half = 0; half < 2; half++) {
                    float c0 = (half ? ccB0[2] + ccB1[2] : ccB0[0] + ccB1[0]);
                    float c1 = (half ? ccB0[3] + ccB1[3] : ccB0[1] + ccB1[1]);
                    float d0 = fmaf(-2.0f, c0, eB0);
                    float d1 = fmaf(-2.0f, c1, eB1);
                    float cv = (d1 < d0) ? d1 : d0;
                    u32   ck = (d1 < d0) ? kcB + 1 : kcB;
                    if (half == 0) { if (cv < best0) { best0 = cv; idx0 = ck; } }
                    else           { if (cv < best1) { best1 = cv; idx1 = ck; } }
                }
            }
        }

        u64 key0 = pack_key(best0, idx0);
        u64 key1 = pack_key(best1, idx1);
#pragma unroll
        for (int o = 1; o <= 2; o <<= 1) {
            u64 t0 = __shfl_xor_sync(0xFFFFFFFFu, key0, o);
            u64 t1 = __shfl_xor_sync(0xFFFFFFFFu, key1, o);
            if (t0 < key0) key0 = t0;
            if (t1 < key1) key1 = t1;
        }
        __syncthreads();
        if ((lane & 3) == 0) {
            int r0 = wrow + (lane >> 2);
            int i0 = (int)(key0 & 0xFFFFFFFFull);
            int i1 = (int)(key1 & 0xFFFFFFFFull);
            sidx[r0]     = i0;
            sidx[r0 + 8] = i1;
            out[O_IDX + row0 + r0]     = (float)i0;
            out[O_IDX + row0 + r0 + 8] = (float)i1;
            atomicAdd(&g_ni[i0], 1.0f);
            atomicAdd(&g_ni[i1], 1.0f);
        }
        __syncthreads();

        float lacc = 0.0f;
        for (int i = tid; i < BM * 32; i += NTHR) {
            int d2 = i >> 7;
            int m  = i & 127;
            u32 sw = SW128((u32)(m * 128 + d2 * 4));
            u32 w0 = *reinterpret_cast<u32*>(sm + A_OFF + sw);
            u32 w1 = *reinterpret_cast<u32*>(sm + A_OFF + 16384 + sw);
            u32 w2 = *reinterpret_cast<u32*>(sm + A_OFF + 32768 + sw);
            float zlo = bf_lo(w0) + bf_lo(w1) + bf_lo(w2);
            float zhi = bf_hi(w0) + bf_hi(w1) + bf_hi(w2);
            int idx = sidx[m];
            int d = d2 * 2;
            float2 q = __ldg(reinterpret_cast<const float2*>(emb + (size_t)idx * DIM + d));
            float dlo = q.x - zlo, dhi = q.y - zhi;
            lacc += dlo * dlo + dhi * dhi;
            int row = row0 + m;
            int b = row >> 10, hw = row & 1023;
            size_t obase = ((size_t)(b * DIM + d) << 10) + hw;
            out[O_QV + obase]        = zlo + dlo;
            out[O_QV + obase + 1024] = zhi + dhi;
            atomicAdd(&g_dw[idx * DIM + d],     zlo);
            atomicAdd(&g_dw[idx * DIM + d + 1], zhi);
        }
#pragma unroll
        for (int o = 16; o > 0; o >>= 1) lacc += __shfl_xor_sync(0xFFFFFFFFu, lacc, o);
        if (lane == 0) lred[wid] = lacc;
        __syncthreads();
        if (tid == 0) {
            float s = 0.0f;
#pragma unroll
            for (int w = 0; w < NTHR / 32; w++) s += lred[w];
            atomicAdd(&g_loss, s);
        }
    } else {
        // =================== FFMA2 path (fma pipe) =======================
        float* zs  = reinterpret_cast<float*>(sm + A_OFF);     // [64][128] fp32
        float* es  = reinterpret_cast<float*>(sm + B_OFF);     // [64][64]
        u64*  smin = reinterpret_cast<u64*>(sm + B_OFF);       // alias (post)
        int*  sidx = reinterpret_cast<int*>(sm + B_OFF + BM * 8);
        float* lred = reinterpret_cast<float*>(sm + EE_OFF);
        const int tx = tid & 15;
        const int ty = tid >> 4;

        for (int i = tid; i < BM * 16; i += NTHR) {
            int m  = (i & 15) | ((i >> 8) << 4);
            int dq = (i >> 4) & 15;
            float4 v = *reinterpret_cast<const float4*>(z + (size_t)(row0 + m) * DIM + dq * 4);
            zs[(dq * 4 + 0) * BM + m] = v.x;
            zs[(dq * 4 + 1) * BM + m] = v.y;
            zs[(dq * 4 + 2) * BM + m] = v.z;
            zs[(dq * 4 + 3) * BM + m] = v.w;
        }

        float    best[8];
        unsigned bidx[8];
#pragma unroll
        for (int r = 0; r < 8; r++) { best[r] = 3.4e38f; bidx[r] = 0u; }

        for (int c = 0; c < 16; c++) {
            const int k0 = c * 64;
            __syncthreads();
            for (int i = tid; i < 64 * 16; i += NTHR) {
                int kk = (i & 15) | ((i >> 8) << 4);
                int dq = (i >> 4) & 15;
                float4 v = *reinterpret_cast<const float4*>(emb + (size_t)(k0 + kk) * DIM + dq * 4);
                es[(dq * 4 + 0) * 64 + kk] = v.x;
                es[(dq * 4 + 1) * 64 + kk] = v.y;
                es[(dq * 4 + 2) * 64 + kk] = v.z;
                es[(dq * 4 + 3) * 64 + kk] = v.w;
            }
            __syncthreads();

            u64 acc[16];
#pragma unroll
            for (int i = 0; i < 16; i++) acc[i] = 0ULL;

            const float* zp_base = zs + ty * 8;
            const float* ep_base = es + tx * 4;
#pragma unroll 4
            for (int d = 0; d < DIM; d++) {
                float4 za = *reinterpret_cast<const float4*>(zp_base + d * BM);
                float4 zb = *reinterpret_cast<const float4*>(zp_base + d * BM + 4);
                float4 ef = *reinterpret_cast<const float4*>(ep_base + d * 64);
                u64 zp0 = pk2(za.x, za.y), zp1 = pk2(za.z, za.w);
                u64 zp2 = pk2(zb.x, zb.y), zp3 = pk2(zb.z, zb.w);
                u64 e0 = dup_f(ef.x), e1 = dup_f(ef.y), e2 = dup_f(ef.z), e3 = dup_f(ef.w);
                fma2(acc[0],  zp0, e0); fma2(acc[1],  zp1, e0);
                fma2(acc[2],  zp2, e0); fma2(acc[3],  zp3, e0);
                fma2(acc[4],  zp0, e1); fma2(acc[5],  zp1, e1);
                fma2(acc[6],  zp2, e1); fma2(acc[7],  zp3, e1);
                fma2(acc[8],  zp0, e2); fma2(acc[9],  zp1, e2);
                fma2(acc[10], zp2, e2); fma2(acc[11], zp3, e2);
                fma2(acc[12], zp0, e3); fma2(acc[13], zp1, e3);
                fma2(acc[14], zp2, e3); fma2(acc[15], zp3, e3);
            }

            float eek[4];
#pragma unroll
            for (int j = 0; j < 4; j++) eek[j] = __ldg(&g_ee[k0 + tx * 4 + j]);
#pragma unroll
            for (int j = 0; j < 4; j++) {
#pragma unroll
                for (int p = 0; p < 4; p++) {
                    float d0, d1;
                    unpk(acc[j * 4 + p], d0, d1);
                    float dist0 = fmaf(-2.0f, d0, eek[j]);
                    float dist1 = fmaf(-2.0f, d1, eek[j]);
                    unsigned kj = (unsigned)(k0 + tx * 4 + j);
                    if (dist0 < best[2 * p])     { best[2 * p]     = dist0; bidx[2 * p]     = kj; }
                    if (dist1 < best[2 * p + 1]) { best[2 * p + 1] = dist1; bidx[2 * p + 1] = kj; }
                }
            }
        }

        __syncthreads();
        if (tid < BM) smin[tid] = 0xFFFFFFFFFFFFFFFFULL;
        __syncthreads();
#pragma unroll
        for (int r = 0; r < 8; r++) {
            u64 key = pack_key(best[r], bidx[r]);
            atomicMin(&smin[ty * 8 + r], key);
        }
        __syncthreads();

        if (tid < BM) {
            int idx = (int)(smin[tid] & 0xFFFFFFFFull);
            sidx[tid] = idx;
            out[O_IDX + row0 + tid] = (float)idx;
            atomicAdd(&g_ni[idx], 1.0f);
        }
        __syncthreads();

        float lacc = 0.0f;
        for (int i = tid; i < BM * DIM; i += NTHR) {
            int m = i & (BM - 1);
            int d = i >> 7;
            int row = row0 + m;
            int idx = sidx[m];
            float zv = zs[d * BM + m];
            float q  = __ldg(&emb[(size_t)idx * DIM + d]);
            float diff = q - zv;
            lacc += diff * diff;
            int b  = row >> 10;
            int hw = row & 1023;
            out[O_QV + (((size_t)(b * DIM + d)) << 10) + hw] = zv + diff;
            atomicAdd(&g_dw[idx * DIM + d], zv);
        }
#pragma unroll
        for (int o = 16; o > 0; o >>= 1) lacc += __shfl_xor_sync(0xFFFFFFFFu, lacc, o);
        if (lane == 0) lred[wid] = lacc;
        __syncthreads();
        if (tid == 0) {
            float s = 0.0f;
#pragma unroll
            for (int w = 0; w < NTHR / 32; w++) s += lred[w];
            atomicAdd(&g_loss, s);
        }
    }
}

// ---------------------------------------------------------------------------
// Kernel 2: smoothing + EMA + new embeddings
// ---------------------------------------------------------------------------
__global__ __launch_bounds__(256)
void k_final(const float* __restrict__ cs, const float* __restrict__ ema,
             float* __restrict__ out) {
    __shared__ float red[8];
    const int tid = threadIdx.x;

    float part = 0.0f;
#pragma unroll
    for (int k = tid; k < KCODES; k += 256)
        part += cs[k] * 0.99f + g_ni[k] * 0.01f;
#pragma unroll
    for (int o = 16; o > 0; o >>= 1) part += __shfl_xor_sync(0xFFFFFFFFu, part, o);
    if ((tid & 31) == 0) red[tid >> 5] = part;
    __syncthreads();
    float n = 0.0f;
#pragma unroll
    for (int w = 0; w < 8; w++) n += red[w];

    if (blockIdx.x == 0 && tid == 0)
        out[O_LOSS] = 0.25f * g_loss / 2097152.0f;

    const int i0 = (blockIdx.x * 256 + tid) * 4;
    const int k  = i0 >> 6;
    float raw = cs[k] * 0.99f + g_ni[k] * 0.01f;
    float smooth = (raw + 1e-5f) / (n + 1024.0f * 1e-5f) * n;
    if ((i0 & 63) == 0) out[O_CL + k] = smooth;

    float4 ev = *reinterpret_cast<const float4*>(ema + i0);
    float4 dv = *reinterpret_cast<const float4*>(g_dw + i0);
    float inv = 1.0f / smooth;
    float ne0 = ev.x * 0.99f + dv.x * 0.01f;
    float ne1 = ev.y * 0.99f + dv.y * 0.01f;
    float ne2 = ev.z * 0.99f + dv.z * 0.01f;
    float ne3 = ev.w * 0.99f + dv.w * 0.01f;
    out[O_EMA + i0 + 0] = ne0;  out[O_EMB + i0 + 0] = ne0 * inv;
    out[O_EMA + i0 + 1] = ne1;  out[O_EMB + i0 + 1] = ne1 * inv;
    out[O_EMA + i0 + 2] = ne2;  out[O_EMB + i0 + 2] = ne2 * inv;
    out[O_EMA + i0 + 3] = ne3;  out[O_EMB + i0 + 3] = ne3 * inv;
}

// ---------------------------------------------------------------------------
extern "C" void kernel_launch(void* const* d_in, const int* in_sizes, int n_in,
                              void* d_out, int out_size) {
    const float* z   = (const float*)d_in[0];
    const float* emb = (const float*)d_in[1];
    const float* cs  = (const float*)d_in[2];
    const float* ema = (const float*)d_in[3];
    float* out = (float*)d_out;

    static bool attr_set = false;
    if (!attr_set) {
        cudaFuncSetAttribute(k_main, cudaFuncAttributeMaxDynamicSharedMemorySize, SMEM_SZ);
        attr_set = true;
    }

    k_prep<<<64, 256>>>(emb);
    k_main<<<N_TOT / BM, NTHR, SMEM_SZ>>>(z, emb, out);
    k_final<<<64, 256>>>(cs, ema, out);
}

// round 10
// speedup vs baseline: 1.6532x; 1.6532x over previous
#include <cuda_runtime.h>
#include <cuda_fp16.h>
#include <cstdint>

#define N_TOT  32768
#define DIM    64
#define KCODES 1024
#define BM     128
#define NTHR   256
#define NCHUNK 8      // 1024 codes / 128 per chunk
#define NCK    128

// output offsets (float32 elements), concatenated in reference return order
#define O_QV   0
#define O_IDX  2097152
#define O_LOSS 2129920
#define O_EMB  2129921     // ODD offset -> scalar stores only
#define O_CL   2195457
#define O_EMA  2196481     // ODD offset -> scalar stores only

typedef unsigned long long u64;
typedef unsigned int u32;

// ---- scratch (__device__ globals; no allocations allowed) ----
__device__ float g_dw[KCODES * DIM];
__device__ float g_ni[KCODES];
__device__ float g_ee[KCODES];
__device__ float g_loss;
__device__ uint4 g_esplit[2][KCODES * 8];   // 2 fp16 split terms, [1024 codes][128B rows]

// ---- smem layout (dynamic, 69632 B -> 2 blocks/SM comfortably) ----
#define A_OFF    0          // 2 x 16KB fp16 A tiles (SW128), z split
#define B_OFF    32768      // 2 x 16KB fp16 B tiles (SW128), e split chunk
#define EE_OFF   65536      // 1024 floats ||e||^2
#define SMEM_SZ  69632

#define SW128(b) ((b) ^ (((b) >> 3) & 0x70))

__device__ __forceinline__ u32 smem_u32(const void* p) {
    u32 a;
    asm("{ .reg .u64 t; cvta.to.shared.u64 t, %1; cvt.u32.u64 %0, t; }" : "=r"(a) : "l"(p));
    return a;
}
#define LDSM_X4(r, addr) \
    asm volatile("ldmatrix.sync.aligned.m8n8.x4.shared.b16 {%0,%1,%2,%3}, [%4];" \
        : "=r"((r)[0]), "=r"((r)[1]), "=r"((r)[2]), "=r"((r)[3]) : "r"(addr))
#define MMA_F16(c, a, b0, b1) \
    asm volatile("mma.sync.aligned.m16n8k16.row.col.f32.f16.f16.f32 " \
        "{%0,%1,%2,%3}, {%4,%5,%6,%7}, {%8,%9}, {%0,%1,%2,%3};" \
        : "+f"((c)[0]), "+f"((c)[1]), "+f"((c)[2]), "+f"((c)[3]) \
        : "r"((a)[0]), "r"((a)[1]), "r"((a)[2]), "r"((a)[3]), \
          "r"(b0), "r"(b1))

// 2-way fp16 split: x ~= h0 + h1, residual ~2^-22 |x|
__device__ __forceinline__ void split2(float x, u32& h0, u32& h1) {
    __half a = __float2half_rn(x);
    float f0 = __half2float(a);
    __half b = __float2half_rn(x - f0);
    h0 = (u32)__half_as_ushort(a);
    h1 = (u32)__half_as_ushort(b);
}
__device__ __forceinline__ float hf_lo(u32 w) {
    return __half2float(__ushort_as_half((unsigned short)(w & 0xffffu)));
}
__device__ __forceinline__ float hf_hi(u32 w) {
    return __half2float(__ushort_as_half((unsigned short)(w >> 16)));
}
__device__ __forceinline__ u64 pack_key(float v, u32 k) {
    u32 u = __float_as_uint(v);
    u = (u & 0x80000000u) ? ~u : (u | 0x80000000u);
    return ((u64)u << 32) | (u64)k;
}

// ---------------------------------------------------------------------------
// Kernel 0: zero scratch, ||e||^2, split embeddings into 2 fp16 arrays
// ---------------------------------------------------------------------------
__global__ void k_prep(const float* __restrict__ emb) {
    int t = blockIdx.x * blockDim.x + threadIdx.x;   // 16384 threads
    reinterpret_cast<float4*>(g_dw)[t] = make_float4(0.f, 0.f, 0.f, 0.f);
    {
        int code = t >> 4, dq = t & 15;
        float4 v = __ldg(reinterpret_cast<const float4*>(emb) + t);
        u32 h0[4], h1[4];
        split2(v.x, h0[0], h1[0]);
        split2(v.y, h0[1], h1[1]);
        split2(v.z, h0[2], h1[2]);
        split2(v.w, h0[3], h1[3]);
        u32 base = code * 32 + dq * 2;
        u32* p0 = reinterpret_cast<u32*>(g_esplit[0]);
        u32* p1 = reinterpret_cast<u32*>(g_esplit[1]);
        p0[base] = h0[0] | (h0[1] << 16);  p0[base + 1] = h0[2] | (h0[3] << 16);
        p1[base] = h1[0] | (h1[1] << 16);  p1[base + 1] = h1[2] | (h1[3] << 16);
    }
    if (t < KCODES) {
        g_ni[t] = 0.0f;
        const float4* e4 = reinterpret_cast<const float4*>(emb + (size_t)t * DIM);
        float s = 0.0f;
#pragma unroll
        for (int i = 0; i < 16; i++) {
            float4 v = e4[i];
            s += v.x * v.x + v.y * v.y + v.z * v.z + v.w * v.w;
        }
        g_ee[t] = s;
    }
    if (t == 0) g_loss = 0.0f;
}

// ---------------------------------------------------------------------------
// Kernel 1: HMMA distances (3-term fp16 split) + argmin + fused epilogue
// ---------------------------------------------------------------------------
__global__ __launch_bounds__(NTHR, 2)
void k_main(const float* __restrict__ z, const float* __restrict__ emb,
            float* __restrict__ out) {
    extern __shared__ __align__(16) unsigned char sm[];
    int*   sidx = reinterpret_cast<int*>(sm + B_OFF);     // alias B (post-loop)
    float* lred = reinterpret_cast<float*>(sm + B_OFF + 2048);
    float* ees  = reinterpret_cast<float*>(sm + EE_OFF);

    const u32 smb = smem_u32(sm);
    const int tid  = threadIdx.x;
    const int lane = tid & 31;
    const int wid  = tid >> 5;
    const int wrow = wid * 16;
    const int row0 = blockIdx.x * BM;

    // ---- stage ||e||^2 into smem
    for (int i = tid; i < KCODES; i += NTHR) ees[i] = __ldg(&g_ee[i]);

    // ---- build 2 fp16 A tiles from z (SW128, [128 rows][64 d])
    for (int i = tid; i < BM * 16; i += NTHR) {
        int m = i >> 4, dq = i & 15;
        float4 v = *reinterpret_cast<const float4*>(z + (size_t)(row0 + m) * DIM + dq * 4);
        u32 h0[4], h1[4];
        split2(v.x, h0[0], h1[0]);
        split2(v.y, h0[1], h1[1]);
        split2(v.z, h0[2], h1[2]);
        split2(v.w, h0[3], h1[3]);
        u32 sw = SW128((u32)(m * 128 + dq * 8));
        u32* d0 = reinterpret_cast<u32*>(sm + A_OFF + sw);
        u32* d1 = reinterpret_cast<u32*>(sm + A_OFF + 16384 + sw);
        d0[0] = h0[0] | (h0[1] << 16);  d0[1] = h0[2] | (h0[3] << 16);
        d1[0] = h1[0] | (h1[1] << 16);  d1[1] = h1[2] | (h1[3] << 16);
    }
    __syncthreads();

    // ---- load A fragments into registers (persist for whole kernel)
    u32 afr[2][4][4];
    {
        int g = lane >> 3;
        int arow = wrow + (g & 1) * 8 + (lane & 7);
        int acol = (g >> 1) * 16;
#pragma unroll
        for (int t = 0; t < 2; t++)
#pragma unroll
            for (int kt = 0; kt < 4; kt++) {
                u32 addr = smb + A_OFF + t * 16384 +
                           SW128((u32)(arow * 128 + kt * 32 + acol));
                LDSM_X4(afr[t][kt], addr);
            }
    }

    float best0 = 3.4e38f, best1 = 3.4e38f;
    u32   idx0 = 0, idx1 = 0;

    // B x4 addressing: lanes 0-15 -> tile A (rows p*16..+7), 16-31 -> tile B (+8)
    const int brow    = lane & 7;
    const int bcolsel = ((lane >> 3) & 1) * 16;
    const int btile   = (lane >> 4) * 8;

    for (int c = 0; c < NCHUNK; c++) {
        __syncthreads();   // previous chunk's ldmatrix reads done
        // ---- stage B chunk (2 terms x 128 codes x 128B) swizzled
        for (int u = tid; u < 2048; u += NTHR) {
            int term = u >> 10;
            int rem  = u & 1023;
            int krow = rem >> 3;
            int seg  = rem & 7;
            uint4 v = __ldg(&g_esplit[term][(c * NCK + krow) * 8 + seg]);
            u32 sw = SW128((u32)(krow * 128 + seg * 16));
            *reinterpret_cast<uint4*>(sm + B_OFF + term * 16384 + sw) = v;
        }
        __syncthreads();

        for (int p = 0; p < 8; p++) {        // n-tile pairs: tiles 2p, 2p+1
            float ccA0[4] = {0, 0, 0, 0}, ccA1[4] = {0, 0, 0, 0};
            float ccB0[4] = {0, 0, 0, 0}, ccB1[4] = {0, 0, 0, 0};
            int rbase = (p * 16 + btile + brow) * 128 + bcolsel;

#pragma unroll
            for (int h = 0; h < 2; h++) {    // k-halves: kt {2h, 2h+1}
                // 4 LDSM_X4: [term][kt-in-half]; regs 0,1 = tileA, 2,3 = tileB
                u32 bb[2][2][4];
#pragma unroll
                for (int t = 0; t < 2; t++)
#pragma unroll
                    for (int q = 0; q < 2; q++) {
                        int kt = h * 2 + q;
                        u32 addr = smb + B_OFF + t * 16384 +
                                   SW128((u32)(rbase + kt * 32));
                        LDSM_X4(bb[t][q], addr);
                    }
#pragma unroll
                for (int q = 0; q < 2; q++) {
                    int kt = h * 2 + q;
                    // 3 terms: (0,1)->cc0, (1,0)->cc1, (0,0)->cc0 (small first)
                    MMA_F16(ccA0, afr[0][kt], bb[1][q][0], bb[1][q][1]);
                    MMA_F16(ccB0, afr[0][kt], bb[1][q][2], bb[1][q][3]);
                    MMA_F16(ccA1, afr[1][kt], bb[0][q][0], bb[0][q][1]);
                    MMA_F16(ccB1, afr[1][kt], bb[0][q][2], bb[0][q][3]);
                    MMA_F16(ccA0, afr[0][kt], bb[0][q][0], bb[0][q][1]);
                    MMA_F16(ccB0, afr[0][kt], bb[0][q][2], bb[0][q][3]);
                }
            }

            // dist = ||e||^2 - 2*dot; rows lane>>2 (+8), cols 2*(lane&3)+{0,1}
            u32 kcA = (u32)(c * NCK + p * 16 + 2 * (lane & 3));
            u32 kcB = kcA + 8;
            float eA0 = ees[kcA], eA1 = ees[kcA + 1];
            float eB0 = ees[kcB], eB1 = ees[kcB + 1];
            {
                float d0 = fmaf(-2.0f, ccA0[0] + ccA1[0], eA0);
                float d1 = fmaf(-2.0f, ccA0[1] + ccA1[1], eA1);
                float cv = (d1 < d0) ? d1 : d0;
                u32   ck = (d1 < d0) ? kcA + 1 : kcA;
                if (cv < best0) { best0 = cv; idx0 = ck; }
                float d2 = fmaf(-2.0f, ccA0[2] + ccA1[2], eA0);
                float d3 = fmaf(-2.0f, ccA0[3] + ccA1[3], eA1);
                float cw = (d3 < d2) ? d3 : d2;
                u32   cx = (d3 < d2) ? kcA + 1 : kcA;
                if (cw < best1) { best1 = cw; idx1 = cx; }
            }
            {
                float d0 = fmaf(-2.0f, ccB0[0] + ccB1[0], eB0);
                float d1 = fmaf(-2.0f, ccB0[1] + ccB1[1], eB1);
                float cv = (d1 < d0) ? d1 : d0;
                u32   ck = (d1 < d0) ? kcB + 1 : kcB;
                if (cv < best0) { best0 = cv; idx0 = ck; }
                float d2 = fmaf(-2.0f, ccB0[2] + ccB1[2], eB0);
                float d3 = fmaf(-2.0f, ccB0[3] + ccB1[3], eB1);
                float cw = (d3 < d2) ? d3 : d2;
                u32   cx = (d3 < d2) ? kcB + 1 : kcB;
                if (cw < best1) { best1 = cw; idx1 = cx; }
            }
        }
    }

    // ---- reduce argmin across the 4 lanes sharing each row
    u64 key0 = pack_key(best0, idx0);
    u64 key1 = pack_key(best1, idx1);
#pragma unroll
    for (int o = 1; o <= 2; o <<= 1) {
        u64 t0 = __shfl_xor_sync(0xFFFFFFFFu, key0, o);
        u64 t1 = __shfl_xor_sync(0xFFFFFFFFu, key1, o);
        if (t0 < key0) key0 = t0;
        if (t1 < key1) key1 = t1;
    }
    __syncthreads();   // all mainloop B reads complete -> safe to alias
    if ((lane & 3) == 0) {
        int r0 = wrow + (lane >> 2);
        int i0 = (int)(key0 & 0xFFFFFFFFull);
        int i1 = (int)(key1 & 0xFFFFFFFFull);
        sidx[r0]     = i0;
        sidx[r0 + 8] = i1;
        out[O_IDX + row0 + r0]     = (float)i0;
        out[O_IDX + row0 + r0 + 8] = (float)i1;
        atomicAdd(&g_ni[i0], 1.0f);
        atomicAdd(&g_ni[i1], 1.0f);
    }
    __syncthreads();

    // ---- fused epilogue: reconstruct z from A tiles (z = h0+h1, ~2^-22 err)
    float lacc = 0.0f;
    for (int i = tid; i < BM * 32; i += NTHR) {   // (d-pair, m): m fast
        int d2 = i >> 7;          // 0..31 -> d = 2*d2
        int m  = i & 127;
        u32 sw = SW128((u32)(m * 128 + d2 * 4));
        u32 w0 = *reinterpret_cast<u32*>(sm + A_OFF + sw);
        u32 w1 = *reinterpret_cast<u32*>(sm + A_OFF + 16384 + sw);
        float zlo = hf_lo(w0) + hf_lo(w1);
        float zhi = hf_hi(w0) + hf_hi(w1);
        int idx = sidx[m];
        int d = d2 * 2;
        float2 q = __ldg(reinterpret_cast<const float2*>(emb + (size_t)idx * DIM + d));
        float dlo = q.x - zlo, dhi = q.y - zhi;
        lacc += dlo * dlo + dhi * dhi;
        int row = row0 + m;
        int b = row >> 10, hw = row & 1023;
        size_t obase = ((size_t)(b * DIM + d) << 10) + hw;
        out[O_QV + obase]        = zlo + dlo;
        out[O_QV + obase + 1024] = zhi + dhi;
        atomicAdd(&g_dw[idx * DIM + d],     zlo);
        atomicAdd(&g_dw[idx * DIM + d + 1], zhi);
    }
#pragma unroll
    for (int o = 16; o > 0; o >>= 1) lacc += __shfl_xor_sync(0xFFFFFFFFu, lacc, o);
    if (lane == 0) lred[wid] = lacc;
    __syncthreads();
    if (tid == 0) {
        float s = 0.0f;
#pragma unroll
        for (int w = 0; w < NTHR / 32; w++) s += lred[w];
        atomicAdd(&g_loss, s);
    }
}

// ---------------------------------------------------------------------------
// Kernel 2: smoothing + EMA + new embeddings
// ---------------------------------------------------------------------------
__global__ __launch_bounds__(256)
void k_final(const float* __restrict__ cs, const float* __restrict__ ema,
             float* __restrict__ out) {
    __shared__ float red[8];
    const int tid = threadIdx.x;

    float part = 0.0f;
#pragma unroll
    for (int k = tid; k < KCODES; k += 256)
        part += cs[k] * 0.99f + g_ni[k] * 0.01f;
#pragma unroll
    for (int o = 16; o > 0; o >>= 1) part += __shfl_xor_sync(0xFFFFFFFFu, part, o);
    if ((tid & 31) == 0) red[tid >> 5] = part;
    __syncthreads();
    float n = 0.0f;
#pragma unroll
    for (int w = 0; w < 8; w++) n += red[w];

    if (blockIdx.x == 0 && tid == 0)
        out[O_LOSS] = 0.25f * g_loss / 2097152.0f;

    const int i0 = (blockIdx.x * 256 + tid) * 4;
    const int k  = i0 >> 6;
    float raw = cs[k] * 0.99f + g_ni[k] * 0.01f;
    float smooth = (raw + 1e-5f) / (n + 1024.0f * 1e-5f) * n;
    if ((i0 & 63) == 0) out[O_CL + k] = smooth;

    float4 ev = *reinterpret_cast<const float4*>(ema + i0);
    float4 dv = *reinterpret_cast<const float4*>(g_dw + i0);
    float inv = 1.0f / smooth;
    float ne0 = ev.x * 0.99f + dv.x * 0.01f;
    float ne1 = ev.y * 0.99f + dv.y * 0.01f;
    float ne2 = ev.z * 0.99f + dv.z * 0.01f;
    float ne3 = ev.w * 0.99f + dv.w * 0.01f;
    out[O_EMA + i0 + 0] = ne0;  out[O_EMB + i0 + 0] = ne0 * inv;
    out[O_EMA + i0 + 1] = ne1;  out[O_EMB + i0 + 1] = ne1 * inv;
    out[O_EMA + i0 + 2] = ne2;  out[O_EMB + i0 + 2] = ne2 * inv;
    out[O_EMA + i0 + 3] = ne3;  out[O_EMB + i0 + 3] = ne3 * inv;
}

// ---------------------------------------------------------------------------
extern "C" void kernel_launch(void* const* d_in, const int* in_sizes, int n_in,
                              void* d_out, int out_size) {
    const float* z   = (const float*)d_in[0];
    const float* emb = (const float*)d_in[1];
    const float* cs  = (const float*)d_in[2];
    const float* ema = (const float*)d_in[3];
    float* out = (float*)d_out;

    static bool attr_set = false;
    if (!attr_set) {
        cudaFuncSetAttribute(k_main, cudaFuncAttributeMaxDynamicSharedMemorySize, SMEM_SZ);
        attr_set = true;
    }

    k_prep<<<64, 256>>>(emb);
    k_main<<<N_TOT / BM, NTHR, SMEM_SZ>>>(z, emb, out);
    k_final<<<64, 256>>>(cs, ema, out);
}

// round 11
// speedup vs baseline: 1.7461x; 1.0562x over previous
#include <cuda_runtime.h>
#include <cuda_fp16.h>
#include <cstdint>

#define N_TOT  32768
#define DIM    64
#define KCODES 1024
#define BM     128
#define NTHR   256
#define NCHUNK 8      // 1024 codes / 128 per chunk
#define NCK    128

// output offsets (float32 elements), concatenated in reference return order
#define O_QV   0
#define O_IDX  2097152
#define O_LOSS 2129920
#define O_EMB  2129921     // ODD offset -> scalar stores only
#define O_CL   2195457
#define O_EMA  2196481     // ODD offset -> scalar stores only

typedef unsigned long long u64;
typedef unsigned int u32;

// ---- scratch (__device__ globals; no allocations allowed) ----
__device__ float g_dw[KCODES * DIM];
__device__ float g_ni[KCODES];
__device__ float g_ee[KCODES];
__device__ float g_loss;
__device__ uint4 g_esplit[2][KCODES * 8];   // 2 fp16 split terms, [1024 codes][128B rows]

// ---- smem layout (dynamic, 102400 B -> 2 blocks/SM) ----
#define A_OFF    0          // 2 x 16KB fp16 A tiles (SW128), z split
#define B_OFF    32768      // 2 x (2 x 16KB) fp16 B tiles (double buffered)
#define EE_OFF   98304      // 1024 floats ||e||^2
#define SMEM_SZ  102400

#define SW128(b) ((b) ^ (((b) >> 3) & 0x70))

__device__ __forceinline__ u32 smem_u32(const void* p) {
    u32 a;
    asm("{ .reg .u64 t; cvta.to.shared.u64 t, %1; cvt.u32.u64 %0, t; }" : "=r"(a) : "l"(p));
    return a;
}
#define LDSM_X4(r, addr) \
    asm volatile("ldmatrix.sync.aligned.m8n8.x4.shared.b16 {%0,%1,%2,%3}, [%4];" \
        : "=r"((r)[0]), "=r"((r)[1]), "=r"((r)[2]), "=r"((r)[3]) : "r"(addr))
#define MMA_F16(c, a, b0, b1) \
    asm volatile("mma.sync.aligned.m16n8k16.row.col.f32.f16.f16.f32 " \
        "{%0,%1,%2,%3}, {%4,%5,%6,%7}, {%8,%9}, {%0,%1,%2,%3};" \
        : "+f"((c)[0]), "+f"((c)[1]), "+f"((c)[2]), "+f"((c)[3]) \
        : "r"((a)[0]), "r"((a)[1]), "r"((a)[2]), "r"((a)[3]), \
          "r"(b0), "r"(b1))
#define CP_ASYNC16(dst, src) \
    asm volatile("cp.async.cg.shared.global [%0], [%1], 16;" :: "r"(dst), "l"(src))
#define CP_COMMIT() asm volatile("cp.async.commit_group;" ::: "memory")
#define CP_WAIT(n)  asm volatile("cp.async.wait_group %0;" :: "n"(n) : "memory")

// 2-way fp16 split: x ~= h0 + h1, residual ~2^-22 |x|
__device__ __forceinline__ void split2(float x, u32& h0, u32& h1) {
    __half a = __float2half_rn(x);
    float f0 = __half2float(a);
    __half b = __float2half_rn(x - f0);
    h0 = (u32)__half_as_ushort(a);
    h1 = (u32)__half_as_ushort(b);
}
__device__ __forceinline__ float hf_lo(u32 w) {
    return __half2float(__ushort_as_half((unsigned short)(w & 0xffffu)));
}
__device__ __forceinline__ float hf_hi(u32 w) {
    return __half2float(__ushort_as_half((unsigned short)(w >> 16)));
}
__device__ __forceinline__ u64 pack_key(float v, u32 k) {
    u32 u = __float_as_uint(v);
    u = (u & 0x80000000u) ? ~u : (u | 0x80000000u);
    return ((u64)u << 32) | (u64)k;
}

// ---------------------------------------------------------------------------
// Kernel 0: zero scratch, ||e||^2, split embeddings into 2 fp16 arrays
// ---------------------------------------------------------------------------
__global__ void k_prep(const float* __restrict__ emb) {
    int t = blockIdx.x * blockDim.x + threadIdx.x;   // 16384 threads
    reinterpret_cast<float4*>(g_dw)[t] = make_float4(0.f, 0.f, 0.f, 0.f);
    {
        int code = t >> 4, dq = t & 15;
        float4 v = __ldg(reinterpret_cast<const float4*>(emb) + t);
        u32 h0[4], h1[4];
        split2(v.x, h0[0], h1[0]);
        split2(v.y, h0[1], h1[1]);
        split2(v.z, h0[2], h1[2]);
        split2(v.w, h0[3], h1[3]);
        u32 base = code * 32 + dq * 2;
        u32* p0 = reinterpret_cast<u32*>(g_esplit[0]);
        u32* p1 = reinterpret_cast<u32*>(g_esplit[1]);
        p0[base] = h0[0] | (h0[1] << 16);  p0[base + 1] = h0[2] | (h0[3] << 16);
        p1[base] = h1[0] | (h1[1] << 16);  p1[base + 1] = h1[2] | (h1[3] << 16);
    }
    if (t < KCODES) {
        g_ni[t] = 0.0f;
        const float4* e4 = reinterpret_cast<const float4*>(emb + (size_t)t * DIM);
        float s = 0.0f;
#pragma unroll
        for (int i = 0; i < 16; i++) {
            float4 v = e4[i];
            s += v.x * v.x + v.y * v.y + v.z * v.z + v.w * v.w;
        }
        g_ee[t] = s;
    }
    if (t == 0) g_loss = 0.0f;
}

// ---------------------------------------------------------------------------
// Kernel 1: HMMA distances (3-term fp16 split), cp.async double-buffered B
// ---------------------------------------------------------------------------
__global__ __launch_bounds__(NTHR, 2)
void k_main(const float* __restrict__ z, const float* __restrict__ emb,
            float* __restrict__ out) {
    extern __shared__ __align__(16) unsigned char sm[];
    int*   sidx = reinterpret_cast<int*>(sm + B_OFF);     // alias B (post-loop)
    float* lred = reinterpret_cast<float*>(sm + B_OFF + 2048);
    float* ees  = reinterpret_cast<float*>(sm + EE_OFF);

    const u32 smb = smem_u32(sm);
    const int tid  = threadIdx.x;
    const int lane = tid & 31;
    const int wid  = tid >> 5;
    const int wrow = wid * 16;
    const int row0 = blockIdx.x * BM;

    // ---- stage ||e||^2 into smem
    for (int i = tid; i < KCODES; i += NTHR) ees[i] = __ldg(&g_ee[i]);

    // ---- prefetch chunk 0 B into buffer 0 (cp.async, 8 x 16B per thread)
#pragma unroll
    for (int u = tid; u < 2048; u += NTHR) {
        int term = u >> 10;
        int rem  = u & 1023;
        int krow = rem >> 3;
        int seg  = rem & 7;
        const uint4* src = &g_esplit[term][(size_t)krow * 8 + seg];
        u32 dst = smb + B_OFF + term * 16384 + SW128((u32)(krow * 128 + seg * 16));
        CP_ASYNC16(dst, src);
    }
    CP_COMMIT();

    // ---- build 2 fp16 A tiles from z (SW128, [128 rows][64 d])
    for (int i = tid; i < BM * 16; i += NTHR) {
        int m = i >> 4, dq = i & 15;
        float4 v = *reinterpret_cast<const float4*>(z + (size_t)(row0 + m) * DIM + dq * 4);
        u32 h0[4], h1[4];
        split2(v.x, h0[0], h1[0]);
        split2(v.y, h0[1], h1[1]);
        split2(v.z, h0[2], h1[2]);
        split2(v.w, h0[3], h1[3]);
        u32 sw = SW128((u32)(m * 128 + dq * 8));
        u32* d0 = reinterpret_cast<u32*>(sm + A_OFF + sw);
        u32* d1 = reinterpret_cast<u32*>(sm + A_OFF + 16384 + sw);
        d0[0] = h0[0] | (h0[1] << 16);  d0[1] = h0[2] | (h0[3] << 16);
        d1[0] = h1[0] | (h1[1] << 16);  d1[1] = h1[2] | (h1[3] << 16);
    }
    __syncthreads();

    // ---- load A fragments into registers (persist for whole kernel)
    u32 afr[2][4][4];
    {
        int g = lane >> 3;
        int arow = wrow + (g & 1) * 8 + (lane & 7);
        int acol = (g >> 1) * 16;
#pragma unroll
        for (int t = 0; t < 2; t++)
#pragma unroll
            for (int kt = 0; kt < 4; kt++) {
                u32 addr = smb + A_OFF + t * 16384 +
                           SW128((u32)(arow * 128 + kt * 32 + acol));
                LDSM_X4(afr[t][kt], addr);
            }
    }

    float best0 = 3.4e38f, best1 = 3.4e38f;
    u32   idx0 = 0, idx1 = 0;

    // B x4 addressing: lanes 0-15 -> tile A (rows p*16..+7), 16-31 -> tile B (+8)
    const int brow    = lane & 7;
    const int bcolsel = ((lane >> 3) & 1) * 16;
    const int btile   = (lane >> 4) * 8;

    for (int c = 0; c < NCHUNK; c++) {
        const u32 bufc = smb + B_OFF + (u32)(c & 1) * 32768;

        __syncthreads();   // protect buffer (c+1)&1 from stragglers in chunk c-1
        if (c < NCHUNK - 1) {
            int cn = c + 1;
            u32 bufn = smb + B_OFF + (u32)(cn & 1) * 32768;
#pragma unroll
            for (int u = tid; u < 2048; u += NTHR) {
                int term = u >> 10;
                int rem  = u & 1023;
                int krow = rem >> 3;
                int seg  = rem & 7;
                const uint4* src = &g_esplit[term][(size_t)(cn * NCK + krow) * 8 + seg];
                u32 dst = bufn + term * 16384 + SW128((u32)(krow * 128 + seg * 16));
                CP_ASYNC16(dst, src);
            }
            CP_COMMIT();
            CP_WAIT(1);    // chunk c's group complete (one group still in flight)
        } else {
            CP_WAIT(0);    // last chunk: drain all
        }
        __syncthreads();

        for (int p = 0; p < 8; p++) {        // n-tile pairs: tiles 2p, 2p+1
            float ccA0[4] = {0, 0, 0, 0}, ccA1[4] = {0, 0, 0, 0};
            float ccB0[4] = {0, 0, 0, 0}, ccB1[4] = {0, 0, 0, 0};
            int rbase = (p * 16 + btile + brow) * 128 + bcolsel;

#pragma unroll
            for (int h = 0; h < 2; h++) {    // k-halves: kt {2h, 2h+1}
                u32 bb[2][2][4];
#pragma unroll
                for (int t = 0; t < 2; t++)
#pragma unroll
                    for (int q = 0; q < 2; q++) {
                        int kt = h * 2 + q;
                        u32 addr = bufc + t * 16384 + SW128((u32)(rbase + kt * 32));
                        LDSM_X4(bb[t][q], addr);
                    }
#pragma unroll
                for (int q = 0; q < 2; q++) {
                    int kt = h * 2 + q;
                    // 3 terms: (0,1)->cc0, (1,0)->cc1, (0,0)->cc0 (small first)
                    MMA_F16(ccA0, afr[0][kt], bb[1][q][0], bb[1][q][1]);
                    MMA_F16(ccB0, afr[0][kt], bb[1][q][2], bb[1][q][3]);
                    MMA_F16(ccA1, afr[1][kt], bb[0][q][0], bb[0][q][1]);
                    MMA_F16(ccB1, afr[1][kt], bb[0][q][2], bb[0][q][3]);
                    MMA_F16(ccA0, afr[0][kt], bb[0][q][0], bb[0][q][1]);
                    MMA_F16(ccB0, afr[0][kt], bb[0][q][2], bb[0][q][3]);
                }
            }

            // dist = ||e||^2 - 2*dot; rows lane>>2 (+8), cols 2*(lane&3)+{0,1}
            u32 kcA = (u32)(c * NCK + p * 16 + 2 * (lane & 3));
            u32 kcB = kcA + 8;
            float eA0 = ees[kcA], eA1 = ees[kcA + 1];
            float eB0 = ees[kcB], eB1 = ees[kcB + 1];
            {
                float d0 = fmaf(-2.0f, ccA0[0] + ccA1[0], eA0);
                float d1 = fmaf(-2.0f, ccA0[1] + ccA1[1], eA1);
                float cv = (d1 < d0) ? d1 : d0;
                u32   ck = (d1 < d0) ? kcA + 1 : kcA;
                if (cv < best0) { best0 = cv; idx0 = ck; }
                float d2 = fmaf(-2.0f, ccA0[2] + ccA1[2], eA0);
                float d3 = fmaf(-2.0f, ccA0[3] + ccA1[3], eA1);
                float cw = (d3 < d2) ? d3 : d2;
                u32   cx = (d3 < d2) ? kcA + 1 : kcA;
                if (cw < best1) { best1 = cw; idx1 = cx; }
            }
            {
                float d0 = fmaf(-2.0f, ccB0[0] + ccB1[0], eB0);
                float d1 = fmaf(-2.0f, ccB0[1] + ccB1[1], eB1);
                float cv = (d1 < d0) ? d1 : d0;
                u32   ck = (d1 < d0) ? kcB + 1 : kcB;
                if (cv < best0) { best0 = cv; idx0 = ck; }
                float d2 = fmaf(-2.0f, ccB0[2] + ccB1[2], eB0);
                float d3 = fmaf(-2.0f, ccB0[3] + ccB1[3], eB1);
                float cw = (d3 < d2) ? d3 : d2;
                u32   cx = (d3 < d2) ? kcB + 1 : kcB;
                if (cw < best1) { best1 = cw; idx1 = cx; }
            }
        }
    }

    // ---- reduce argmin across the 4 lanes sharing each row
    u64 key0 = pack_key(best0, idx0);
    u64 key1 = pack_key(best1, idx1);
#pragma unroll
    for (int o = 1; o <= 2; o <<= 1) {
        u64 t0 = __shfl_xor_sync(0xFFFFFFFFu, key0, o);
        u64 t1 = __shfl_xor_sync(0xFFFFFFFFu, key1, o);
        if (t0 < key0) key0 = t0;
        if (t1 < key1) key1 = t1;
    }
    __syncthreads();   // all mainloop B reads complete -> safe to alias
    if ((lane & 3) == 0) {
        int r0 = wrow + (lane >> 2);
        int i0 = (int)(key0 & 0xFFFFFFFFull);
        int i1 = (int)(key1 & 0xFFFFFFFFull);
        sidx[r0]     = i0;
        sidx[r0 + 8] = i1;
        out[O_IDX + row0 + r0]     = (float)i0;
        out[O_IDX + row0 + r0 + 8] = (float)i1;
        atomicAdd(&g_ni[i0], 1.0f);
        atomicAdd(&g_ni[i1], 1.0f);
    }
    __syncthreads();

    // ---- fused epilogue: reconstruct z from A tiles (z = h0+h1, ~2^-22 err)
    float lacc = 0.0f;
    for (int i = tid; i < BM * 32; i += NTHR) {   // (d-pair, m): m fast
        int d2 = i >> 7;          // 0..31 -> d = 2*d2
        int m  = i & 127;
        u32 sw = SW128((u32)(m * 128 + d2 * 4));
        u32 w0 = *reinterpret_cast<u32*>(sm + A_OFF + sw);
        u32 w1 = *reinterpret_cast<u32*>(sm + A_OFF + 16384 + sw);
        float zlo = hf_lo(w0) + hf_lo(w1);
        float zhi = hf_hi(w0) + hf_hi(w1);
        int idx = sidx[m];
        int d = d2 * 2;
        float2 q = __ldg(reinterpret_cast<const float2*>(emb + (size_t)idx * DIM + d));
        float dlo = q.x - zlo, dhi = q.y - zhi;
        lacc += dlo * dlo + dhi * dhi;
        int row = row0 + m;
        int b = row >> 10, hw = row & 1023;
        size_t obase = ((size_t)(b * DIM + d) << 10) + hw;
        out[O_QV + obase]        = zlo + dlo;
        out[O_QV + obase + 1024] = zhi + dhi;
        atomicAdd(&g_dw[idx * DIM + d],     zlo);
        atomicAdd(&g_dw[idx * DIM + d + 1], zhi);
    }
#pragma unroll
    for (int o = 16; o > 0; o >>= 1) lacc += __shfl_xor_sync(0xFFFFFFFFu, lacc, o);
    if (lane == 0) lred[wid] = lacc;
    __syncthreads();
    if (tid == 0) {
        float s = 0.0f;
#pragma unroll
        for (int w = 0; w < NTHR / 32; w++) s += lred[w];
        atomicAdd(&g_loss, s);
    }
}

// ---------------------------------------------------------------------------
// Kernel 2: smoothing + EMA + new embeddings
// ---------------------------------------------------------------------------
__global__ __launch_bounds__(256)
void k_final(const float* __restrict__ cs, const float* __restrict__ ema,
             float* __restrict__ out) {
    __shared__ float red[8];
    const int tid = threadIdx.x;

    float part = 0.0f;
#pragma unroll
    for (int k = tid; k < KCODES; k += 256)
        part += cs[k] * 0.99f + g_ni[k] * 0.01f;
#pragma unroll
    for (int o = 16; o > 0; o >>= 1) part += __shfl_xor_sync(0xFFFFFFFFu, part, o);
    if ((tid & 31) == 0) red[tid >> 5] = part;
    __syncthreads();
    float n = 0.0f;
#pragma unroll
    for (int w = 0; w < 8; w++) n += red[w];

    if (blockIdx.x == 0 && tid == 0)
        out[O_LOSS] = 0.25f * g_loss / 2097152.0f;

    const int i0 = (blockIdx.x * 256 + tid) * 4;
    const int k  = i0 >> 6;
    float raw = cs[k] * 0.99f + g_ni[k] * 0.01f;
    float smooth = (raw + 1e-5f) / (n + 1024.0f * 1e-5f) * n;
    if ((i0 & 63) == 0) out[O_CL + k] = smooth;

    float4 ev = *reinterpret_cast<const float4*>(ema + i0);
    float4 dv = *reinterpret_cast<const float4*>(g_dw + i0);
    float inv = 1.0f / smooth;
    float ne0 = ev.x * 0.99f + dv.x * 0.01f;
    float ne1 = ev.y * 0.99f + dv.y * 0.01f;
    float ne2 = ev.z * 0.99f + dv.z * 0.01f;
    float ne3 = ev.w * 0.99f + dv.w * 0.01f;
    out[O_EMA + i0 + 0] = ne0;  out[O_EMB + i0 + 0] = ne0 * inv;
    out[O_EMA + i0 + 1] = ne1;  out[O_EMB + i0 + 1] = ne1 * inv;
    out[O_EMA + i0 + 2] = ne2;  out[O_EMB + i0 + 2] = ne2 * inv;
    out[O_EMA + i0 + 3] = ne3;  out[O_EMB + i0 + 3] = ne3 * inv;
}

// ---------------------------------------------------------------------------
extern "C" void kernel_launch(void* const* d_in, const int* in_sizes, int n_in,
                              void* d_out, int out_size) {
    const float* z   = (const float*)d_in[0];
    const float* emb = (const float*)d_in[1];
    const float* cs  = (const float*)d_in[2];
    const float* ema = (const float*)d_in[3];
    float* out = (float*)d_out;

    static bool attr_set = false;
    if (!attr_set) {
        cudaFuncSetAttribute(k_main, cudaFuncAttributeMaxDynamicSharedMemorySize, SMEM_SZ);
        attr_set = true;
    }

    k_prep<<<64, 256>>>(emb);
    k_main<<<N_TOT / BM, NTHR, SMEM_SZ>>>(z, emb, out);
    k_final<<<64, 256>>>(cs, ema, out);
}